// round 1
// baseline (speedup 1.0000x reference)
#include <cuda_runtime.h>
#include <cstdint>

// Problem constants (match reference)
#define BATCH    8192
#define FEAT_DIM 2048
#define NUM_CLASSES 751

// Scratch: per-row clamped squared distance + label-width flag.
__device__ float g_rowdist[BATCH];
__device__ int   g_label_is_i64;

// ---------------------------------------------------------------------------
// Kernel 0: detect whether the labels buffer is int64 or int32.
// If int64 (little-endian), words at odd int32 indices are the high halves of
// values in [0, 751) -> all zero. If int32 random labels, the odd-index words
// are themselves labels; P(4096 consecutive labels == 0) ~ 0.
// Only inspect the first BATCH/2 pairs so we never read past an int32 buffer.
// ---------------------------------------------------------------------------
__global__ void detect_label_width_kernel(const int* __restrict__ labels_i32) {
    __shared__ int s_nonzero;
    if (threadIdx.x == 0) s_nonzero = 0;
    __syncthreads();
    for (int i = threadIdx.x; i < BATCH / 2; i += blockDim.x) {
        if (labels_i32[2 * i + 1] != 0) s_nonzero = 1;  // benign race, monotone
    }
    __syncthreads();
    if (threadIdx.x == 0) g_label_is_i64 = s_nonzero ? 0 : 1;
}

// ---------------------------------------------------------------------------
// Kernel 1: one block per batch row. Compute ||x_b - c_{label_b}||^2 over
// FEAT_DIM, clamp, store to g_rowdist[b]. float4 loads, coalesced on x;
// centers (6 MB) live in L2 and are reused ~11x.
// ---------------------------------------------------------------------------
__global__ void __launch_bounds__(256, 8)
row_distance_kernel(const float* __restrict__ x,
                    const int*   __restrict__ labels_any,
                    const float* __restrict__ centers) {
    const int b = blockIdx.x;

    long long lbl;
    if (g_label_is_i64) {
        lbl = __ldg(((const long long*)labels_any) + b);
    } else {
        lbl = (long long)__ldg(labels_any + b);
    }

    const float4* __restrict__ xr = (const float4*)(x + (size_t)b * FEAT_DIM);
    const float4* __restrict__ cr = (const float4*)(centers + (size_t)lbl * FEAT_DIM);

    // FEAT_DIM/4 = 512 float4 per row; 256 threads -> 2 each.
    float acc = 0.0f;
    #pragma unroll
    for (int i = threadIdx.x; i < FEAT_DIM / 4; i += 256) {
        float4 a = __ldg(xr + i);
        float4 c = __ldg(cr + i);
        float d0 = a.x - c.x;
        float d1 = a.y - c.y;
        float d2 = a.z - c.z;
        float d3 = a.w - c.w;
        acc += d0 * d0 + d1 * d1 + d2 * d2 + d3 * d3;
    }

    // Warp reduce
    #pragma unroll
    for (int off = 16; off > 0; off >>= 1)
        acc += __shfl_down_sync(0xFFFFFFFFu, acc, off);

    __shared__ float s_warp[8];
    const int lane = threadIdx.x & 31;
    const int wid  = threadIdx.x >> 5;
    if (lane == 0) s_warp[wid] = acc;
    __syncthreads();

    if (wid == 0) {
        float v = (lane < 8) ? s_warp[lane] : 0.0f;
        #pragma unroll
        for (int off = 4; off > 0; off >>= 1)
            v += __shfl_down_sync(0xFFFFFFFFu, v, off);
        if (lane == 0) {
            // clamp to [1e-12, 1e12] exactly as the reference does
            v = fminf(fmaxf(v, 1e-12f), 1e12f);
            g_rowdist[b] = v;
        }
    }
}

// ---------------------------------------------------------------------------
// Kernel 2: deterministic single-block reduction of the 8192 row distances,
// add the (C-1) clamped-zero contribution per row, divide by BATCH.
// ---------------------------------------------------------------------------
__global__ void __launch_bounds__(1024, 1)
final_reduce_kernel(float* __restrict__ out) {
    __shared__ float s_red[1024];
    float acc = 0.0f;
    // 8192 / 1024 = 8 elements per thread, pairwise-ish ordering is fixed.
    #pragma unroll
    for (int i = threadIdx.x; i < BATCH; i += 1024)
        acc += g_rowdist[i];
    s_red[threadIdx.x] = acc;
    __syncthreads();
    #pragma unroll
    for (int s = 512; s > 0; s >>= 1) {
        if (threadIdx.x < s) s_red[threadIdx.x] += s_red[threadIdx.x + s];
        __syncthreads();
    }
    if (threadIdx.x == 0) {
        // masked-out entries: B*(C-1) zeros clipped to 1e-12 each
        const float clipped_zeros = (float)BATCH * (float)(NUM_CLASSES - 1) * 1e-12f;
        out[0] = (s_red[0] + clipped_zeros) / (float)BATCH;
    }
}

extern "C" void kernel_launch(void* const* d_in, const int* in_sizes, int n_in,
                              void* d_out, int out_size) {
    const float* x       = (const float*)d_in[0];
    const int*   labels  = (const int*)d_in[1];   // width detected at runtime
    const float* centers = (const float*)d_in[2];
    float*       out     = (float*)d_out;

    detect_label_width_kernel<<<1, 256>>>(labels);
    row_distance_kernel<<<BATCH, 256>>>(x, labels, centers);
    final_reduce_kernel<<<1, 1024>>>(out);
}